// round 10
// baseline (speedup 1.0000x reference)
#include <cuda_runtime.h>
#include <cstdint>

// Problem shape (fixed by the dataset)
#define B_BATCH 4
#define E_EDGES 320000
#define N_NODES 10000
#define F_FEAT  64

#define THREADS       512
#define CHUNK_EDGES   256                         // 64KB of msg per chunk
#define NSTAGES       3
#define CHUNKS_PER_B  (E_EDGES / CHUNK_EDGES)     // 1250 (exact)
#define TOTAL_CHUNKS  (CHUNKS_PER_B * B_BATCH)    // 5000
#define NCTAS         148

#define MSG_STAGE_BYTES (CHUNK_EDGES * 64 * 4)    // 65536
#define IDX_STAGE_BYTES (CHUNK_EDGES * 4)         // 1024
#define SMEM_BYTES (NSTAGES * (MSG_STAGE_BYTES + IDX_STAGE_BYTES))  // 199680

__device__ __forceinline__ void cpasync16(uint32_t saddr, const void* gptr) {
    asm volatile("cp.async.cg.shared.global [%0], [%1], 16;"
                 :: "r"(saddr), "l"(gptr) : "memory");
}
#define CP_COMMIT() asm volatile("cp.async.commit_group;" ::: "memory")
#define CP_WAIT2()  asm volatile("cp.async.wait_group 2;" ::: "memory")

// Persistent pipelined scatter-add.
// Loads are cp.async (fire-and-forget, L1-bypassing): RED backpressure at L2
// cannot stall the DRAM read stream; up to 2 future 64KB chunks are always in
// flight per SM. Consumers read staged data via LDS and issue no-return
// red.global.add.v4.f32.
__global__ __launch_bounds__(THREADS, 1) void scatter_pipe_kernel(
    const float4* __restrict__ msg,   // [B*E, 16] float4 (batches contiguous)
    const int*    __restrict__ idx,   // [B*E]
    float*        __restrict__ out)   // [B, N, 64]
{
    extern __shared__ __align__(128) char smem[];
    const uint32_t sbase = (uint32_t)__cvta_generic_to_shared(smem);
    const int tid = threadIdx.x;

    auto issue = [&](int c, int st) {
        // msg: 4096 float4, 8 per thread, coalesced
        const float4* g = msg + (long long)c * (CHUNK_EDGES * 16);
        const uint32_t ms = sbase + st * MSG_STAGE_BYTES;
#pragma unroll
        for (int i = 0; i < 8; ++i) {
            const int j = tid + i * THREADS;
            cpasync16(ms + j * 16, g + j);
        }
        // idx: 256 ints = 64 x 16B
        if (tid < 64) {
            const uint32_t is = sbase + NSTAGES * MSG_STAGE_BYTES + st * IDX_STAGE_BYTES;
            cpasync16(is + tid * 16, idx + (long long)c * CHUNK_EDGES + tid * 4);
        }
    };

    // Prologue: stages 0 .. NSTAGES-2
#pragma unroll
    for (int p = 0; p < NSTAGES - 1; ++p) {
        const int c = blockIdx.x + p * NCTAS;
        if (c < TOTAL_CHUNKS) issue(c, p);
        CP_COMMIT();
    }

    for (int k = 0;; ++k) {
        const int c = blockIdx.x + k * NCTAS;
        if (c >= TOTAL_CHUNKS) break;

        // Issue the future chunk first (into the stage consumed at iter k-1).
        const int cf = blockIdx.x + (k + NSTAGES - 1) * NCTAS;
        if (cf < TOTAL_CHUNKS) issue(cf, (k + NSTAGES - 1) % NSTAGES);
        CP_COMMIT();

        CP_WAIT2();          // chunk k's group complete (<= NSTAGES-1 pending)
        __syncthreads();     // cross-thread smem visibility

        // Consume stage k%NSTAGES
        const int st = k % NSTAGES;
        const int b  = c / CHUNKS_PER_B;           // chunks never straddle batches
        const float4* smsg = reinterpret_cast<const float4*>(smem + st * MSG_STAGE_BYTES);
        const int*    sidx = reinterpret_cast<const int*>(
            smem + NSTAGES * MSG_STAGE_BYTES + st * IDX_STAGE_BYTES);
        float* outb = out + (long long)b * N_NODES * F_FEAT;

#pragma unroll
        for (int i = 0; i < 8; ++i) {
            const int j    = tid + i * THREADS;    // 0..4095
            const int edge = j >> 4;
            const int f4   = j & 15;
            const float4 v = smsg[j];              // LDS.128, conflict-free
            const int node = sidx[edge];           // broadcast within 16 lanes
            float* dst = outb + node * F_FEAT + f4 * 4;
            asm volatile(
                "red.global.add.v4.f32 [%0], {%1, %2, %3, %4};"
                :: "l"(dst), "f"(v.x), "f"(v.y), "f"(v.z), "f"(v.w)
                : "memory");
        }
        __syncthreads();     // stage free before it is re-filled next iter
    }
}

extern "C" void kernel_launch(void* const* d_in, const int* in_sizes, int n_in,
                              void* d_out, int out_size) {
    const float4* msg = (const float4*)d_in[0];   // msg_vectors [B,E,F] f32
    const int*    idx = (const int*)d_in[1];      // start_indices [B,E] i32
    // d_in[2] = h_v, unused by the reference computation
    float* out = (float*)d_out;                   // [B,N,F] f32

    // Allow 192KB+ dynamic smem (idempotent; not a stream op, capture-safe)
    static bool attr_set = false;
    if (!attr_set) {
        cudaFuncSetAttribute(scatter_pipe_kernel,
                             cudaFuncAttributeMaxDynamicSharedMemorySize, SMEM_BYTES);
        attr_set = true;
    }

    // 1) zero the output (harness poisons it with 0xAA)
    cudaMemsetAsync(out, 0, (size_t)out_size * sizeof(float), 0);

    // 2) persistent pipelined scatter-add
    scatter_pipe_kernel<<<NCTAS, THREADS, SMEM_BYTES>>>(msg, idx, out);
}